// round 4
// baseline (speedup 1.0000x reference)
#include <cuda_runtime.h>
#include <cuda_bf16.h>
#include <cstdint>

// ---------------------------------------------------------------------------
// Problem constants
// ---------------------------------------------------------------------------
#define BATCH   64
#define SEQ     2048
#define CIN     32
#define WIN     20
#define DIN     (WIN * CIN)      // 640
#define DP      (DIN / 2)        // 320
#define HID     128
#define G4      (4 * HID)        // 512
#define L_OUT   (SEQ - WIN)      // 2028
#define LBL     48

// ---------------------------------------------------------------------------
// Scratch (static __device__ arrays; no cudaMalloc allowed)
// ---------------------------------------------------------------------------
__device__ float g_wc[DIN * G4];                       // combined proj->ih0 weight [d][g]
__device__ float g_bias0[G4];
__device__ float g_xpre[(size_t)BATCH * L_OUT * G4];   // per-step gate preactivations
__device__ float g_hseq[(size_t)BATCH * L_OUT * HID];  // per-step hidden outputs

// ---------------------------------------------------------------------------
// Packed fp32x2 helpers
// ---------------------------------------------------------------------------
__device__ __forceinline__ unsigned long long pk2(float x, float y) {
    unsigned long long r;
    asm("mov.b64 %0, {%1, %2};" : "=l"(r) : "f"(x), "f"(y));
    return r;
}
__device__ __forceinline__ float2 unpk2(unsigned long long v) {
    float2 r;
    asm("mov.b64 {%0, %1}, %2;" : "=f"(r.x), "=f"(r.y) : "l"(v));
    return r;
}
__device__ __forceinline__ void fma2(unsigned long long& d, unsigned long long a,
                                     unsigned long long b) {
    asm("fma.rn.f32x2 %0, %1, %2, %3;" : "=l"(d) : "l"(a), "l"(b), "l"(d));
}

// ---------------------------------------------------------------------------
// Cluster / mbarrier helpers
// ---------------------------------------------------------------------------
__device__ __forceinline__ unsigned smem_u32(const void* p) {
    return (unsigned)__cvta_generic_to_shared(p);
}
__device__ __forceinline__ unsigned mapa_rank(unsigned addr, unsigned rank) {
    unsigned r;
    asm("mapa.shared::cluster.u32 %0, %1, %2;" : "=r"(r) : "r"(addr), "r"(rank));
    return r;
}
__device__ __forceinline__ void st_cluster_f32(unsigned addr, float v) {
    asm volatile("st.shared::cluster.f32 [%0], %1;" :: "r"(addr), "f"(v) : "memory");
}
__device__ __forceinline__ void mbar_init(unsigned addr, unsigned cnt) {
    asm volatile("mbarrier.init.shared.b64 [%0], %1;" :: "r"(addr), "r"(cnt) : "memory");
}
__device__ __forceinline__ void mbar_arrive_remote(unsigned addr) {
    asm volatile("mbarrier.arrive.release.cluster.shared::cluster.b64 _, [%0];"
                 :: "r"(addr) : "memory");
}
__device__ __forceinline__ void mbar_wait_cluster(unsigned addr, unsigned parity) {
    asm volatile(
        "{\n\t"
        ".reg .pred P1;\n\t"
        "WAIT_%=:\n\t"
        "mbarrier.try_wait.parity.acquire.cluster.shared::cta.b64 P1, [%0], %1, 0x989680;\n\t"
        "@P1 bra.uni DONE_%=;\n\t"
        "bra.uni WAIT_%=;\n\t"
        "DONE_%=:\n\t"
        "}"
        :: "r"(addr), "r"(parity) : "memory");
}
__device__ __forceinline__ void cluster_barrier() {
    asm volatile("barrier.cluster.arrive.aligned;" ::: "memory");
    asm volatile("barrier.cluster.wait.aligned;" ::: "memory");
}

// ---------------------------------------------------------------------------
// Fast activations
// ---------------------------------------------------------------------------
__device__ __forceinline__ float fast_sigmoid(float x) {
    return 1.f / (1.f + __expf(-x));
}

// ---------------------------------------------------------------------------
// Kernel 1: fold projection into layer-0 input weight.
// ---------------------------------------------------------------------------
__global__ void combine_kernel(const float* __restrict__ proj_w,
                               const float* __restrict__ w_ih0) {
    __shared__ float sPW[32][32];
    __shared__ float sWI[32][33];
    int tx = threadIdx.x, ty = threadIdx.y;
    int d0 = blockIdx.x * 32, g0 = blockIdx.y * 32;
    float acc = 0.f;
    for (int p0 = 0; p0 < DP; p0 += 32) {
        sPW[ty][tx] = proj_w[(size_t)(p0 + ty) * DIN + d0 + tx];
        sWI[ty][tx] = w_ih0[(size_t)(g0 + ty) * DP + p0 + tx];
        __syncthreads();
#pragma unroll
        for (int p = 0; p < 32; p++) acc += sPW[p][tx] * sWI[ty][p];
        __syncthreads();
    }
    g_wc[(size_t)(d0 + tx) * G4 + g0 + ty] = acc;
}

__global__ void bias0_kernel(const float* __restrict__ proj_b,
                             const float* __restrict__ w_ih0,
                             const float* __restrict__ b_ih0,
                             const float* __restrict__ b_hh0) {
    int gidx = threadIdx.x;
    float acc = b_ih0[gidx] + b_hh0[gidx];
    const float* wr = w_ih0 + (size_t)gidx * DP;
    for (int p = 0; p < DP; p++) acc += proj_b[p] * wr[p];
    g_bias0[gidx] = acc;
}

// ---------------------------------------------------------------------------
// Kernel 2: layer-0 preactivations (implicit sliding-window GEMM).
// ---------------------------------------------------------------------------
__global__ void __launch_bounds__(256)
xpre0_kernel(const float* __restrict__ in) {
    __shared__ __align__(16) float sIn[128 * 32 + DIN];
    __shared__ __align__(16) float sB[32][64];

    int tid = threadIdx.x;
    int tx = tid & 15, ty = tid >> 4;
    int t0 = blockIdx.x * 128;
    int n0 = blockIdx.y * 64;
    int b  = blockIdx.z;

    const float* inb = in + (size_t)b * SEQ * CIN;
    int base = t0 * CIN;
    for (int i = tid; i < 128 * 32 + DIN; i += 256) {
        int gi = base + i;
        sIn[i] = (gi < SEQ * CIN) ? inb[gi] : 0.f;
    }
    __syncthreads();

    unsigned long long acc[8][2];
#pragma unroll
    for (int i = 0; i < 8; i++) { acc[i][0] = pk2(0.f, 0.f); acc[i][1] = pk2(0.f, 0.f); }

    for (int k0 = 0; k0 < DIN; k0 += 32) {
#pragma unroll
        for (int r = 0; r < 2; r++) {
            int j = tid * 8 + r * 4;
            int kk = j >> 6, nn = j & 63;
            *(float4*)&sB[kk][nn] =
                *(const float4*)&g_wc[(size_t)(k0 + kk) * G4 + n0 + nn];
        }
        __syncthreads();
#pragma unroll
        for (int k = 0; k < 32; k++) {
            ulonglong2 bb = *(const ulonglong2*)&sB[k][tx * 4];
#pragma unroll
            for (int i = 0; i < 8; i++) {
                float a = sIn[(ty * 8 + i) * CIN + k0 + k];
                unsigned long long aa = pk2(a, a);
                fma2(acc[i][0], aa, bb.x);
                fma2(acc[i][1], aa, bb.y);
            }
        }
        __syncthreads();
    }

    float4 bias = *(const float4*)&g_bias0[n0 + tx * 4];
#pragma unroll
    for (int i = 0; i < 8; i++) {
        int t = t0 + ty * 8 + i;
        if (t < L_OUT) {
            float2 p0 = unpk2(acc[i][0]);
            float2 p1 = unpk2(acc[i][1]);
            float4 v = make_float4(p0.x + bias.x, p0.y + bias.y,
                                   p1.x + bias.z, p1.y + bias.w);
            *(float4*)&g_xpre[((size_t)b * L_OUT + t) * G4 + n0 + tx * 4] = v;
        }
    }
}

// ---------------------------------------------------------------------------
// Kernel 3: input preactivations for layers 1..3.
// ---------------------------------------------------------------------------
__global__ void __launch_bounds__(256)
gemm_ih_kernel(const float* __restrict__ w_ih,
               const float* __restrict__ b_ih,
               const float* __restrict__ b_hh) {
    __shared__ __align__(16) float sA[64 * 64];
    __shared__ __align__(16) float sB[64 * 68];

    int tid = threadIdx.x;
    int tx = tid & 15, ty = tid >> 4;
    int t0 = blockIdx.x * 64;
    int n0 = blockIdx.y * 64;
    int b  = blockIdx.z;

    unsigned long long acc[4][2];
#pragma unroll
    for (int i = 0; i < 4; i++) { acc[i][0] = pk2(0.f, 0.f); acc[i][1] = pk2(0.f, 0.f); }

    for (int kt = 0; kt < 2; kt++) {
#pragma unroll
        for (int r = 0; r < 4; r++) {
            int j = tid * 16 + r * 4;
            int row = j >> 6, col = j & 63;
            int t = t0 + row;
            float4 v = make_float4(0.f, 0.f, 0.f, 0.f);
            if (t < L_OUT)
                v = *(const float4*)&g_hseq[((size_t)b * L_OUT + t) * HID + kt * 64 + col];
            *(float4*)&sA[row * 64 + col] = v;
        }
        for (int j = tid; j < 64 * 64; j += 256) {
            int n = j >> 6, kk = j & 63;
            sB[kk * 68 + n] = w_ih[(size_t)(n0 + n) * HID + kt * 64 + kk];
        }
        __syncthreads();
#pragma unroll
        for (int k = 0; k < 64; k++) {
            ulonglong2 bb = *(const ulonglong2*)&sB[k * 68 + tx * 4];
#pragma unroll
            for (int i = 0; i < 4; i++) {
                float a = sA[(ty * 4 + i) * 64 + k];
                unsigned long long aa = pk2(a, a);
                fma2(acc[i][0], aa, bb.x);
                fma2(acc[i][1], aa, bb.y);
            }
        }
        __syncthreads();
    }

    int n = n0 + tx * 4;
    float4 bias = make_float4(b_ih[n] + b_hh[n], b_ih[n + 1] + b_hh[n + 1],
                              b_ih[n + 2] + b_hh[n + 2], b_ih[n + 3] + b_hh[n + 3]);
#pragma unroll
    for (int i = 0; i < 4; i++) {
        int t = t0 + ty * 4 + i;
        if (t < L_OUT) {
            float2 p0 = unpk2(acc[i][0]);
            float2 p1 = unpk2(acc[i][1]);
            float4 v = make_float4(p0.x + bias.x, p0.y + bias.y,
                                   p1.x + bias.z, p1.y + bias.w);
            *(float4*)&g_xpre[((size_t)b * L_OUT + t) * G4 + n] = v;
        }
    }
}

// ---------------------------------------------------------------------------
// Kernel 4: recurrent scan, unit-sliced 2-CTA cluster per batch element.
//
// CTA rank r owns hidden units [r*64, r*64+64). Thread tid: gate = tid&3
// (i,f,g,o), local unit = tid>>2. Gate exchange via 3 shfl within a warp.
//
// R4 protocol change (fixes the R3 regression): each of the 64 writer
// threads (gate 0) performs st.shared::cluster of its h followed
// IMMEDIATELY by its own mbarrier.arrive.release.cluster on the peer's
// barrier (count=64). Per-thread release ordering covers the thread's own
// remote store — NO fence.acq_rel.cluster, and the arrive is no longer
// delayed behind __syncthreads, so the ~275cyc DSMEM transit overlaps the
// end-of-step __syncthreads and the peer's dot_own. Visibility of
// non-writer reads before the writer's arrive is ordered by the shfl.sync
// chain (writer consumes non-writers' gate values; all 4 gates of a unit
// share one warp).
//
// Wait schedule (validated in R3): step t waits on bar[(t-1)&1] with
// parity ((t-1)>>1)&1 — the arrive at end of step s lands on bar[s&1] and
// is 0-based arrival s>>1 of that barrier.
// ---------------------------------------------------------------------------
template<int LO>
__device__ __forceinline__ void dot_half(unsigned long long& a0, unsigned long long& a1,
                                         const unsigned long long* w2, const float* hb) {
    const ulonglong2* h2 = (const ulonglong2*)(hb + LO);
#pragma unroll
    for (int k = 0; k < 16; k++) {
        ulonglong2 u = h2[k];
        fma2(a0, w2[LO / 2 + 2 * k], u.x);
        fma2(a1, w2[LO / 2 + 2 * k + 1], u.y);
    }
}

template<int OWN_LO>
__device__ __forceinline__ void scan_body(const float* __restrict__ w_hh, int b,
                                          float (*hbuf)[HID],
                                          unsigned long long* mbars) {
    constexpr int PEER_LO = (OWN_LO == 0) ? 64 : 0;
    const unsigned peer = (OWN_LO == 0) ? 1u : 0u;

    int tid  = threadIdx.x;
    int gate = tid & 3;
    int ul   = tid >> 2;                 // 0..63
    int unit = OWN_LO + ul;
    int row  = gate * HID + unit;        // gate row in [0,512)

    // recurrent weight row -> registers as f32x2 pairs (constant-indexed)
    unsigned long long w2[64];
    const ulonglong2* wr = (const ulonglong2*)(w_hh + (size_t)row * HID);
#pragma unroll
    for (int k = 0; k < 32; k++) {
        ulonglong2 u = wr[k];
        w2[2 * k]     = u.x;
        w2[2 * k + 1] = u.y;
    }

    if (tid < HID) { hbuf[0][tid] = 0.f; hbuf[1][tid] = 0.f; }
    unsigned bar0 = smem_u32(&mbars[0]);
    unsigned bar1 = smem_u32(&mbars[1]);
    if (tid == 0) { mbar_init(bar0, 64); mbar_init(bar1, 64); }
    __syncthreads();
    cluster_barrier();   // peer mbar init + zeroed h visible cluster-wide

    unsigned peer_hA  = mapa_rank(smem_u32(&hbuf[0][unit]), peer);
    unsigned peer_hB  = mapa_rank(smem_u32(&hbuf[1][unit]), peer);
    unsigned peer_b0  = mapa_rank(bar0, peer);
    unsigned peer_b1  = mapa_rank(bar1, peer);

    const bool  writer    = (gate == 0);
    const float act_scale = (gate == 2) ? 2.f : 1.f;
    const float act_mul   = (gate == 2) ? 2.f : 1.f;
    const float act_add   = (gate == 2) ? -1.f : 0.f;

    float c = 0.f;
    const size_t xrow = (size_t)b * L_OUT;
    float xp  = g_xpre[(xrow + 0) * G4 + row];
    float xp1 = g_xpre[(xrow + 1) * G4 + row];

    for (int t = 0; t < L_OUT; t++) {
        float xp2 = (t + 2 < L_OUT) ? g_xpre[(xrow + t + 2) * G4 + row] : 0.f;

        const float* hb = hbuf[t & 1];
        unsigned long long a0 = pk2(0.f, 0.f), a1 = pk2(0.f, 0.f);

        dot_half<OWN_LO>(a0, a1, w2, hb);           // local half: always ready
        if (t > 0) {
            // sync with peer's arrives during step t-1 on bar[(t-1)&1]
            int s = t - 1;
            mbar_wait_cluster((s & 1) ? bar1 : bar0, (unsigned)((s >> 1) & 1));
        }
        dot_half<PEER_LO>(a0, a1, w2, hb);          // peer half: just arrived

        float2 s0 = unpk2(a0), s1 = unpk2(a1);
        float pre = ((s0.x + s0.y) + (s1.x + s1.y)) + xp;
        float sg  = fast_sigmoid(act_scale * pre);
        float act = fmaf(act_mul, sg, act_add);     // sigmoid (i,f,o) / tanh (g)

        float fv = __shfl_down_sync(0xffffffffu, act, 1);
        float gv = __shfl_down_sync(0xffffffffu, act, 2);
        float ov = __shfl_down_sync(0xffffffffu, act, 3);

        if (writer) {
            c = fmaf(fv, c, act * gv);
            float tc = fmaf(2.f, fast_sigmoid(2.f * c), -1.f);   // tanh(c)
            float h  = ov * tc;
            st_cluster_f32((t & 1) ? peer_hA : peer_hB, h);      // buf[(t+1)&1] remote
            mbar_arrive_remote((t & 1) ? peer_b1 : peer_b0);     // own release, early
            hbuf[(t + 1) & 1][unit] = h;                         // local copy
            g_hseq[(xrow + t) * HID + unit] = h;
        }
        __syncthreads();   // local h(t) visible to all warps for next dot_own
        xp = xp1; xp1 = xp2;
    }
    cluster_barrier();
}

__global__ void __cluster_dims__(2, 1, 1) __launch_bounds__(256, 1)
scan_kernel(const float* __restrict__ w_hh) {
    __shared__ __align__(16) float hbuf[2][HID];
    __shared__ __align__(8) unsigned long long mbars[2];

    int rank = blockIdx.x & 1;
    int b    = blockIdx.x >> 1;
    if (rank == 0) scan_body<0>(w_hh, b, hbuf, mbars);
    else           scan_body<64>(w_hh, b, hbuf, mbars);
}

// ---------------------------------------------------------------------------
// Kernel 5: readout.
// ---------------------------------------------------------------------------
__global__ void out_kernel(const float* __restrict__ out_w,
                           const float* __restrict__ out_b,
                           float* __restrict__ out) {
    __shared__ float h[HID];
    int b = blockIdx.x;
    if (threadIdx.x < HID)
        h[threadIdx.x] = g_hseq[((size_t)b * L_OUT + (L_OUT - 1)) * HID + threadIdx.x];
    __syncthreads();
    if (threadIdx.x < LBL) {
        float acc = out_b[threadIdx.x];
        const float* wr = out_w + (size_t)threadIdx.x * HID;
#pragma unroll 8
        for (int k = 0; k < HID; k++) acc += wr[k] * h[k];
        out[(size_t)b * LBL + threadIdx.x] = acc;
    }
}

// ---------------------------------------------------------------------------
// Launch
// ---------------------------------------------------------------------------
extern "C" void kernel_launch(void* const* d_in, const int* in_sizes, int n_in,
                              void* d_out, int out_size) {
    const float* inputs    = (const float*)d_in[0];
    const float* proj_w    = (const float*)d_in[4];
    const float* proj_b    = (const float*)d_in[5];
    const float* w_ih0     = (const float*)d_in[6];
    const float* w_hh0     = (const float*)d_in[7];
    const float* b_ih0     = (const float*)d_in[8];
    const float* b_hh0     = (const float*)d_in[9];
    const float* w_ih_rest = (const float*)d_in[10];
    const float* w_hh_rest = (const float*)d_in[11];
    const float* b_ih_rest = (const float*)d_in[12];
    const float* b_hh_rest = (const float*)d_in[13];
    const float* out_w     = (const float*)d_in[14];
    const float* out_b     = (const float*)d_in[15];
    float* out = (float*)d_out;

    combine_kernel<<<dim3(DIN / 32, G4 / 32), dim3(32, 32)>>>(proj_w, w_ih0);
    bias0_kernel<<<1, G4>>>(proj_b, w_ih0, b_ih0, b_hh0);

    xpre0_kernel<<<dim3((L_OUT + 127) / 128, G4 / 64, BATCH), 256>>>(inputs);

    scan_kernel<<<BATCH * 2, 256>>>(w_hh0);

    for (int l = 0; l < 3; l++) {
        gemm_ih_kernel<<<dim3((L_OUT + 63) / 64, G4 / 64, BATCH), 256>>>(
            w_ih_rest + (size_t)l * G4 * HID,
            b_ih_rest + (size_t)l * G4,
            b_hh_rest + (size_t)l * G4);
        scan_kernel<<<BATCH * 2, 256>>>(w_hh_rest + (size_t)l * G4 * HID);
    }

    out_kernel<<<BATCH, 128>>>(out_w, out_b, out);
}

// round 5
// speedup vs baseline: 1.5061x; 1.5061x over previous
#include <cuda_runtime.h>
#include <cuda_bf16.h>
#include <cstdint>

// ---------------------------------------------------------------------------
// Problem constants
// ---------------------------------------------------------------------------
#define BATCH   64
#define SEQ     2048
#define CIN     32
#define WIN     20
#define DIN     (WIN * CIN)      // 640
#define DP      (DIN / 2)        // 320
#define HID     128
#define G4      (4 * HID)        // 512
#define L_OUT   (SEQ - WIN)      // 2028
#define XT      2032             // padded time stride for g_xpre (mult of 8, > L_OUT+3)
#define LBL     48

// ---------------------------------------------------------------------------
// Scratch (static __device__ arrays; no cudaMalloc allowed)
// ---------------------------------------------------------------------------
__device__ float g_wc[DIN * G4];                       // combined proj->ih0 weight [d][g]
__device__ float g_bias0[G4];
__device__ float g_xpre[(size_t)BATCH * G4 * XT];      // preactivations, [b][g][t] (t-major!)
__device__ float g_hseq[(size_t)BATCH * L_OUT * HID];  // per-step hidden outputs [b][t][h]

// ---------------------------------------------------------------------------
// Packed fp32x2 helpers
// ---------------------------------------------------------------------------
__device__ __forceinline__ unsigned long long pk2(float x, float y) {
    unsigned long long r;
    asm("mov.b64 %0, {%1, %2};" : "=l"(r) : "f"(x), "f"(y));
    return r;
}
__device__ __forceinline__ float2 unpk2(unsigned long long v) {
    float2 r;
    asm("mov.b64 {%0, %1}, %2;" : "=f"(r.x), "=f"(r.y) : "l"(v));
    return r;
}
__device__ __forceinline__ void fma2(unsigned long long& d, unsigned long long a,
                                     unsigned long long b) {
    asm("fma.rn.f32x2 %0, %1, %2, %3;" : "=l"(d) : "l"(a), "l"(b), "l"(d));
}

// ---------------------------------------------------------------------------
// Cluster / mbarrier helpers
// ---------------------------------------------------------------------------
__device__ __forceinline__ unsigned smem_u32(const void* p) {
    return (unsigned)__cvta_generic_to_shared(p);
}
__device__ __forceinline__ unsigned mapa_rank(unsigned addr, unsigned rank) {
    unsigned r;
    asm("mapa.shared::cluster.u32 %0, %1, %2;" : "=r"(r) : "r"(addr), "r"(rank));
    return r;
}
__device__ __forceinline__ void st_cluster_f32(unsigned addr, float v) {
    asm volatile("st.shared::cluster.f32 [%0], %1;" :: "r"(addr), "f"(v) : "memory");
}
__device__ __forceinline__ void mbar_init(unsigned addr, unsigned cnt) {
    asm volatile("mbarrier.init.shared.b64 [%0], %1;" :: "r"(addr), "r"(cnt) : "memory");
}
__device__ __forceinline__ void mbar_arrive_remote(unsigned addr) {
    asm volatile("mbarrier.arrive.release.cluster.shared::cluster.b64 _, [%0];"
                 :: "r"(addr) : "memory");
}
__device__ __forceinline__ void mbar_wait_cluster(unsigned addr, unsigned parity) {
    asm volatile(
        "{\n\t"
        ".reg .pred P1;\n\t"
        "WAIT_%=:\n\t"
        "mbarrier.try_wait.parity.acquire.cluster.shared::cta.b64 P1, [%0], %1, 0x989680;\n\t"
        "@P1 bra.uni DONE_%=;\n\t"
        "bra.uni WAIT_%=;\n\t"
        "DONE_%=:\n\t"
        "}"
        :: "r"(addr), "r"(parity) : "memory");
}
__device__ __forceinline__ void cluster_barrier() {
    asm volatile("barrier.cluster.arrive.aligned;" ::: "memory");
    asm volatile("barrier.cluster.wait.aligned;" ::: "memory");
}

// ---------------------------------------------------------------------------
// Fast activations (fp32, ~1e-6 rel error)
// ---------------------------------------------------------------------------
__device__ __forceinline__ float fast_sigmoid(float x) {
    return 1.f / (1.f + __expf(-x));
}
__device__ __forceinline__ float fast_tanh(float x) {
    float ax = fabsf(x);
    float e  = __expf(-2.f * ax);
    float r  = __fdividef(1.f - e, 1.f + e);
    return copysignf(r, x);
}

// ---------------------------------------------------------------------------
// Kernel 1: fold projection into layer-0 input weight.
// ---------------------------------------------------------------------------
__global__ void combine_kernel(const float* __restrict__ proj_w,
                               const float* __restrict__ w_ih0) {
    __shared__ float sPW[32][32];
    __shared__ float sWI[32][33];
    int tx = threadIdx.x, ty = threadIdx.y;
    int d0 = blockIdx.x * 32, g0 = blockIdx.y * 32;
    float acc = 0.f;
    for (int p0 = 0; p0 < DP; p0 += 32) {
        sPW[ty][tx] = proj_w[(size_t)(p0 + ty) * DIN + d0 + tx];
        sWI[ty][tx] = w_ih0[(size_t)(g0 + ty) * DP + p0 + tx];
        __syncthreads();
#pragma unroll
        for (int p = 0; p < 32; p++) acc += sPW[p][tx] * sWI[ty][p];
        __syncthreads();
    }
    g_wc[(size_t)(d0 + tx) * G4 + g0 + ty] = acc;
}

__global__ void bias0_kernel(const float* __restrict__ proj_b,
                             const float* __restrict__ w_ih0,
                             const float* __restrict__ b_ih0,
                             const float* __restrict__ b_hh0) {
    int gidx = threadIdx.x;
    float acc = b_ih0[gidx] + b_hh0[gidx];
    const float* wr = w_ih0 + (size_t)gidx * DP;
    for (int p = 0; p < DP; p++) acc += proj_b[p] * wr[p];
    g_bias0[gidx] = acc;
}

// ---------------------------------------------------------------------------
// Kernel 2: layer-0 preactivations (implicit sliding-window GEMM).
// Output transposed: g_xpre[b][g][t] — each thread owns 8 consecutive t for
// each of 4 n, so stores remain full-sector STG.128 pairs.
// ---------------------------------------------------------------------------
__global__ void __launch_bounds__(256)
xpre0_kernel(const float* __restrict__ in) {
    __shared__ __align__(16) float sIn[128 * 32 + DIN];
    __shared__ __align__(16) float sB[32][64];

    int tid = threadIdx.x;
    int tx = tid & 15, ty = tid >> 4;
    int t0 = blockIdx.x * 128;
    int n0 = blockIdx.y * 64;
    int b  = blockIdx.z;

    const float* inb = in + (size_t)b * SEQ * CIN;
    int base = t0 * CIN;
    for (int i = tid; i < 128 * 32 + DIN; i += 256) {
        int gi = base + i;
        sIn[i] = (gi < SEQ * CIN) ? inb[gi] : 0.f;
    }
    __syncthreads();

    unsigned long long acc[8][2];
#pragma unroll
    for (int i = 0; i < 8; i++) { acc[i][0] = pk2(0.f, 0.f); acc[i][1] = pk2(0.f, 0.f); }

    for (int k0 = 0; k0 < DIN; k0 += 32) {
#pragma unroll
        for (int r = 0; r < 2; r++) {
            int j = tid * 8 + r * 4;
            int kk = j >> 6, nn = j & 63;
            *(float4*)&sB[kk][nn] =
                *(const float4*)&g_wc[(size_t)(k0 + kk) * G4 + n0 + nn];
        }
        __syncthreads();
#pragma unroll
        for (int k = 0; k < 32; k++) {
            ulonglong2 bb = *(const ulonglong2*)&sB[k][tx * 4];
#pragma unroll
            for (int i = 0; i < 8; i++) {
                float a = sIn[(ty * 8 + i) * CIN + k0 + k];
                unsigned long long aa = pk2(a, a);
                fma2(acc[i][0], aa, bb.x);
                fma2(acc[i][1], aa, bb.y);
            }
        }
        __syncthreads();
    }

    float4 bias = *(const float4*)&g_bias0[n0 + tx * 4];
    int tbase = t0 + ty * 8;
    if (tbase < XT) {        // tbase multiple of 8 -> tbase+7 <= XT-1
#pragma unroll
        for (int nn = 0; nn < 4; nn++) {
            float bv = (nn == 0) ? bias.x : (nn == 1) ? bias.y : (nn == 2) ? bias.z : bias.w;
            float v[8];
#pragma unroll
            for (int i = 0; i < 8; i++) {
                float2 p = unpk2(acc[i][nn >> 1]);
                v[i] = ((nn & 1) ? p.y : p.x) + bv;
            }
            float* dst = &g_xpre[((size_t)b * G4 + n0 + tx * 4 + nn) * XT + tbase];
            *(float4*)(dst)     = make_float4(v[0], v[1], v[2], v[3]);
            *(float4*)(dst + 4) = make_float4(v[4], v[5], v[6], v[7]);
        }
    }
}

// ---------------------------------------------------------------------------
// Kernel 3: input preactivations for layers 1..3 (transposed output too).
// ---------------------------------------------------------------------------
__global__ void __launch_bounds__(256)
gemm_ih_kernel(const float* __restrict__ w_ih,
               const float* __restrict__ b_ih,
               const float* __restrict__ b_hh) {
    __shared__ __align__(16) float sA[64 * 64];
    __shared__ __align__(16) float sB[64 * 68];

    int tid = threadIdx.x;
    int tx = tid & 15, ty = tid >> 4;
    int t0 = blockIdx.x * 64;
    int n0 = blockIdx.y * 64;
    int b  = blockIdx.z;

    unsigned long long acc[4][2];
#pragma unroll
    for (int i = 0; i < 4; i++) { acc[i][0] = pk2(0.f, 0.f); acc[i][1] = pk2(0.f, 0.f); }

    for (int kt = 0; kt < 2; kt++) {
#pragma unroll
        for (int r = 0; r < 4; r++) {
            int j = tid * 16 + r * 4;
            int row = j >> 6, col = j & 63;
            int t = t0 + row;
            float4 v = make_float4(0.f, 0.f, 0.f, 0.f);
            if (t < L_OUT)
                v = *(const float4*)&g_hseq[((size_t)b * L_OUT + t) * HID + kt * 64 + col];
            *(float4*)&sA[row * 64 + col] = v;
        }
        for (int j = tid; j < 64 * 64; j += 256) {
            int n = j >> 6, kk = j & 63;
            sB[kk * 68 + n] = w_ih[(size_t)(n0 + n) * HID + kt * 64 + kk];
        }
        __syncthreads();
#pragma unroll
        for (int k = 0; k < 64; k++) {
            ulonglong2 bb = *(const ulonglong2*)&sB[k * 68 + tx * 4];
#pragma unroll
            for (int i = 0; i < 4; i++) {
                float a = sA[(ty * 4 + i) * 64 + k];
                unsigned long long aa = pk2(a, a);
                fma2(acc[i][0], aa, bb.x);
                fma2(acc[i][1], aa, bb.y);
            }
        }
        __syncthreads();
    }

    int n = n0 + tx * 4;
    float4 bias = make_float4(b_ih[n] + b_hh[n], b_ih[n + 1] + b_hh[n + 1],
                              b_ih[n + 2] + b_hh[n + 2], b_ih[n + 3] + b_hh[n + 3]);
    int tbase = t0 + ty * 4;
    if (tbase < XT) {        // tbase multiple of 4 -> tbase+3 <= XT-1
#pragma unroll
        for (int nn = 0; nn < 4; nn++) {
            float bv = (nn == 0) ? bias.x : (nn == 1) ? bias.y : (nn == 2) ? bias.z : bias.w;
            float v[4];
#pragma unroll
            for (int i = 0; i < 4; i++) {
                float2 p = unpk2(acc[i][nn >> 1]);
                v[i] = ((nn & 1) ? p.y : p.x) + bv;
            }
            float* dst = &g_xpre[((size_t)b * G4 + n + nn) * XT + tbase];
            *(float4*)(dst) = make_float4(v[0], v[1], v[2], v[3]);
        }
    }
}

// ---------------------------------------------------------------------------
// Kernel 4: recurrent scan — EXACT R1 protocol (measured best), plus:
//   * 4 accumulators in the dot (RAW chain 128 -> 64 cyc)
//   * xpre read from transposed [b][g][t] layout as one LDG.128 per 4 steps
//     (was: one strided 4B LDG per step, 8x sector amplification)
//
// Protocol (R1): rank r owns gate rows [r*256, r*256+256). Each thread
// computes one gate row; both CTAs keep the FULL h redundantly, so the next
// dot has no cross-CTA dependency. Per step: every thread stores its gate
// value to the peer's double-buffered gr[] + arrives on the peer's single
// mbarrier (count=256, parity toggles each step); tid<128 waits, computes
// c,h, writes h_sh.
// ---------------------------------------------------------------------------
__global__ void __cluster_dims__(2, 1, 1) __launch_bounds__(256, 1)
scan_kernel(const float* __restrict__ w_hh) {
    __shared__ float h_sh[HID];
    __shared__ float gl[HID];               // partner gate from own CTA (f or o)
    __shared__ float gr[2][256];            // remote gates, double buffered
    __shared__ __align__(8) unsigned long long mbar;

    int tid  = threadIdx.x;
    int rank = blockIdx.x & 1;
    int b    = blockIdx.x >> 1;
    int g    = rank * 256 + tid;

    // recurrent weight row -> registers as f32x2 pairs
    unsigned long long w2[64];
    const ulonglong2* wr = (const ulonglong2*)(w_hh + (size_t)g * HID);
#pragma unroll
    for (int k = 0; k < 32; k++) {
        ulonglong2 u = wr[k];
        w2[2 * k]     = u.x;
        w2[2 * k + 1] = u.y;
    }

    if (tid < HID) h_sh[tid] = 0.f;
    unsigned bar_a = smem_u32(&mbar);
    if (tid == 0) mbar_init(bar_a, 256);
    __syncthreads();
    cluster_barrier();   // peer mbar init + h_sh visible cluster-wide

    unsigned peer = rank ^ 1;
    unsigned peer_gr0 = mapa_rank(smem_u32(&gr[0][tid]), peer);
    unsigned peer_gr1 = mapa_rank(smem_u32(&gr[1][tid]), peer);
    unsigned peer_bar = mapa_rank(bar_a, peer);

    float c = 0.f;
    unsigned ph = 0;
    const size_t hrow = (size_t)b * L_OUT;
    const float* xrow_p = g_xpre + ((size_t)b * G4 + g) * XT;
    bool is_tanh_gate = (rank == 1) && (tid < HID);

    float4 xcur = *(const float4*)(xrow_p);
    float4 xnxt = *(const float4*)(xrow_p + 4);

    for (int t4 = 0; t4 < L_OUT; t4 += 4) {
        float4 xn2 = make_float4(0.f, 0.f, 0.f, 0.f);
        if (t4 + 8 < XT) xn2 = *(const float4*)(xrow_p + t4 + 8);

#pragma unroll
        for (int s = 0; s < 4; s++) {
            int t = t4 + s;
            float xp = (s == 0) ? xcur.x : (s == 1) ? xcur.y : (s == 2) ? xcur.z : xcur.w;

            // dot(w_row, h): 4 accumulators, packed f32x2
            unsigned long long a0 = pk2(0.f, 0.f), a1 = pk2(0.f, 0.f);
            unsigned long long a2 = pk2(0.f, 0.f), a3 = pk2(0.f, 0.f);
            const ulonglong2* h2 = (const ulonglong2*)h_sh;
#pragma unroll
            for (int k = 0; k < 16; k++) {
                ulonglong2 u = h2[2 * k];
                ulonglong2 v = h2[2 * k + 1];
                fma2(a0, w2[4 * k],     u.x);
                fma2(a1, w2[4 * k + 1], u.y);
                fma2(a2, w2[4 * k + 2], v.x);
                fma2(a3, w2[4 * k + 3], v.y);
            }
            float2 s0 = unpk2(a0), s1 = unpk2(a1), s2 = unpk2(a2), s3 = unpk2(a3);
            float pre = (((s0.x + s0.y) + (s1.x + s1.y)) +
                         ((s2.x + s2.y) + (s3.x + s3.y))) + xp;

            float act = is_tanh_gate ? fast_tanh(pre) : fast_sigmoid(pre);

            // exchange: local partner slot + remote (peer) slot + release-arrive
            if (tid >= HID) gl[tid - HID] = act;
            st_cluster_f32((t & 1) ? peer_gr1 : peer_gr0, act);
            mbar_arrive_remote(peer_bar);
            __syncthreads();   // gl visible; h_sh reads of this step complete

            if (tid < HID) {
                mbar_wait_cluster(bar_a, ph);   // acquire: remote gates visible
                const float* grb = gr[t & 1];
                float iv, fv, gv, ov;
                if (rank == 0) { iv = act;       fv = gl[tid];
                                 gv = grb[tid];  ov = grb[HID + tid]; }
                else           { gv = act;       ov = gl[tid];
                                 iv = grb[tid];  fv = grb[HID + tid]; }
                c = fv * c + iv * gv;
                float h = ov * fast_tanh(c);
                h_sh[tid] = h;
                if (rank == 0)
                    g_hseq[(hrow + t) * HID + tid] = h;
            }
            __syncthreads();   // h_sh(t) ready for next dot
            ph ^= 1;
        }
        xcur = xnxt; xnxt = xn2;
    }
    cluster_barrier();
}

// ---------------------------------------------------------------------------
// Kernel 5: readout.
// ---------------------------------------------------------------------------
__global__ void out_kernel(const float* __restrict__ out_w,
                           const float* __restrict__ out_b,
                           float* __restrict__ out) {
    __shared__ float h[HID];
    int b = blockIdx.x;
    if (threadIdx.x < HID)
        h[threadIdx.x] = g_hseq[((size_t)b * L_OUT + (L_OUT - 1)) * HID + threadIdx.x];
    __syncthreads();
    if (threadIdx.x < LBL) {
        float acc = out_b[threadIdx.x];
        const float* wr = out_w + (size_t)threadIdx.x * HID;
#pragma unroll 8
        for (int k = 0; k < HID; k++) acc += wr[k] * h[k];
        out[(size_t)b * LBL + threadIdx.x] = acc;
    }
}

// ---------------------------------------------------------------------------
// Launch
// ---------------------------------------------------------------------------
extern "C" void kernel_launch(void* const* d_in, const int* in_sizes, int n_in,
                              void* d_out, int out_size) {
    const float* inputs    = (const float*)d_in[0];
    const float* proj_w    = (const float*)d_in[4];
    const float* proj_b    = (const float*)d_in[5];
    const float* w_ih0     = (const float*)d_in[6];
    const float* w_hh0     = (const float*)d_in[7];
    const float* b_ih0     = (const float*)d_in[8];
    const float* b_hh0     = (const float*)d_in[9];
    const float* w_ih_rest = (const float*)d_in[10];
    const float* w_hh_rest = (const float*)d_in[11];
    const float* b_ih_rest = (const float*)d_in[12];
    const float* b_hh_rest = (const float*)d_in[13];
    const float* out_w     = (const float*)d_in[14];
    const float* out_b     = (const float*)d_in[15];
    float* out = (float*)d_out;

    combine_kernel<<<dim3(DIN / 32, G4 / 32), dim3(32, 32)>>>(proj_w, w_ih0);
    bias0_kernel<<<1, G4>>>(proj_b, w_ih0, b_ih0, b_hh0);

    xpre0_kernel<<<dim3((L_OUT + 127) / 128, G4 / 64, BATCH), 256>>>(inputs);

    scan_kernel<<<BATCH * 2, 256>>>(w_hh0);

    for (int l = 0; l < 3; l++) {
        gemm_ih_kernel<<<dim3((L_OUT + 63) / 64, G4 / 64, BATCH), 256>>>(
            w_ih_rest + (size_t)l * G4 * HID,
            b_ih_rest + (size_t)l * G4,
            b_hh_rest + (size_t)l * G4);
        scan_kernel<<<BATCH * 2, 256>>>(w_hh_rest + (size_t)l * G4 * HID);
    }

    out_kernel<<<BATCH, 128>>>(out_w, out_b, out);
}

// round 6
// speedup vs baseline: 1.7492x; 1.1614x over previous
#include <cuda_runtime.h>
#include <cuda_bf16.h>
#include <cstdint>

// ---------------------------------------------------------------------------
// Problem constants
// ---------------------------------------------------------------------------
#define BATCH   64
#define SEQ     2048
#define CIN     32
#define WIN     20
#define DIN     (WIN * CIN)      // 640
#define DP      (DIN / 2)        // 320
#define HID     128
#define G4      (4 * HID)        // 512
#define L_OUT   (SEQ - WIN)      // 2028
#define XT      2032             // padded time stride for g_xpre (mult of 8, > L_OUT+3)
#define LBL     48

// ---------------------------------------------------------------------------
// Scratch (static __device__ arrays; no cudaMalloc allowed)
// ---------------------------------------------------------------------------
__device__ float g_wc[DIN * G4];                       // combined proj->ih0 weight [d][g]
__device__ float g_bias0[G4];
__device__ float g_xpre[(size_t)BATCH * G4 * XT];      // preactivations, [b][g][t] (t-major!)
__device__ float g_hseq[(size_t)BATCH * L_OUT * HID];  // per-step hidden outputs [b][t][h]

// ---------------------------------------------------------------------------
// Packed fp32x2 helpers
// ---------------------------------------------------------------------------
__device__ __forceinline__ unsigned long long pk2(float x, float y) {
    unsigned long long r;
    asm("mov.b64 %0, {%1, %2};" : "=l"(r) : "f"(x), "f"(y));
    return r;
}
__device__ __forceinline__ float2 unpk2(unsigned long long v) {
    float2 r;
    asm("mov.b64 {%0, %1}, %2;" : "=f"(r.x), "=f"(r.y) : "l"(v));
    return r;
}
__device__ __forceinline__ void fma2(unsigned long long& d, unsigned long long a,
                                     unsigned long long b) {
    asm("fma.rn.f32x2 %0, %1, %2, %3;" : "=l"(d) : "l"(a), "l"(b), "l"(d));
}

// ---------------------------------------------------------------------------
// Cluster / mbarrier helpers
// ---------------------------------------------------------------------------
__device__ __forceinline__ unsigned smem_u32(const void* p) {
    return (unsigned)__cvta_generic_to_shared(p);
}
__device__ __forceinline__ unsigned mapa_rank(unsigned addr, unsigned rank) {
    unsigned r;
    asm("mapa.shared::cluster.u32 %0, %1, %2;" : "=r"(r) : "r"(addr), "r"(rank));
    return r;
}
__device__ __forceinline__ void mbar_init(unsigned addr, unsigned cnt) {
    asm volatile("mbarrier.init.shared.b64 [%0], %1;" :: "r"(addr), "r"(cnt) : "memory");
}
__device__ __forceinline__ void mbar_expect_tx(unsigned addr, unsigned bytes) {
    asm volatile("mbarrier.arrive.expect_tx.shared.b64 _, [%0], %1;"
                 :: "r"(addr), "r"(bytes) : "memory");
}
__device__ __forceinline__ void fence_proxy_async_cta() {
    asm volatile("fence.proxy.async.shared::cta;" ::: "memory");
}
__device__ __forceinline__ void bulk_copy_to_peer(unsigned dst_cluster, unsigned src_cta,
                                                  unsigned bytes, unsigned peer_mbar) {
    asm volatile(
        "cp.async.bulk.shared::cluster.shared::cta.mbarrier::complete_tx::bytes "
        "[%0], [%1], %2, [%3];"
        :: "r"(dst_cluster), "r"(src_cta), "r"(bytes), "r"(peer_mbar) : "memory");
}
__device__ __forceinline__ void mbar_wait_cluster(unsigned addr, unsigned parity) {
    asm volatile(
        "{\n\t"
        ".reg .pred P1;\n\t"
        "WAIT_%=:\n\t"
        "mbarrier.try_wait.parity.acquire.cluster.shared::cta.b64 P1, [%0], %1, 0x989680;\n\t"
        "@P1 bra.uni DONE_%=;\n\t"
        "bra.uni WAIT_%=;\n\t"
        "DONE_%=:\n\t"
        "}"
        :: "r"(addr), "r"(parity) : "memory");
}
__device__ __forceinline__ void cluster_barrier() {
    asm volatile("barrier.cluster.arrive.aligned;" ::: "memory");
    asm volatile("barrier.cluster.wait.aligned;" ::: "memory");
}

// ---------------------------------------------------------------------------
// Fast activations (fp32, ~1e-6 rel error)
// ---------------------------------------------------------------------------
__device__ __forceinline__ float fast_sigmoid(float x) {
    return 1.f / (1.f + __expf(-x));
}
__device__ __forceinline__ float fast_tanh(float x) {
    float ax = fabsf(x);
    float e  = __expf(-2.f * ax);
    float r  = __fdividef(1.f - e, 1.f + e);
    return copysignf(r, x);
}

// ---------------------------------------------------------------------------
// Kernel 1: fold projection into layer-0 input weight.
// ---------------------------------------------------------------------------
__global__ void combine_kernel(const float* __restrict__ proj_w,
                               const float* __restrict__ w_ih0) {
    __shared__ float sPW[32][32];
    __shared__ float sWI[32][33];
    int tx = threadIdx.x, ty = threadIdx.y;
    int d0 = blockIdx.x * 32, g0 = blockIdx.y * 32;
    float acc = 0.f;
    for (int p0 = 0; p0 < DP; p0 += 32) {
        sPW[ty][tx] = proj_w[(size_t)(p0 + ty) * DIN + d0 + tx];
        sWI[ty][tx] = w_ih0[(size_t)(g0 + ty) * DP + p0 + tx];
        __syncthreads();
#pragma unroll
        for (int p = 0; p < 32; p++) acc += sPW[p][tx] * sWI[ty][p];
        __syncthreads();
    }
    g_wc[(size_t)(d0 + tx) * G4 + g0 + ty] = acc;
}

__global__ void bias0_kernel(const float* __restrict__ proj_b,
                             const float* __restrict__ w_ih0,
                             const float* __restrict__ b_ih0,
                             const float* __restrict__ b_hh0) {
    int gidx = threadIdx.x;
    float acc = b_ih0[gidx] + b_hh0[gidx];
    const float* wr = w_ih0 + (size_t)gidx * DP;
    for (int p = 0; p < DP; p++) acc += proj_b[p] * wr[p];
    g_bias0[gidx] = acc;
}

// ---------------------------------------------------------------------------
// Kernel 2: layer-0 preactivations (implicit sliding-window GEMM).
// Output transposed: g_xpre[b][g][t].
// ---------------------------------------------------------------------------
__global__ void __launch_bounds__(256)
xpre0_kernel(const float* __restrict__ in) {
    __shared__ __align__(16) float sIn[128 * 32 + DIN];
    __shared__ __align__(16) float sB[32][64];

    int tid = threadIdx.x;
    int tx = tid & 15, ty = tid >> 4;
    int t0 = blockIdx.x * 128;
    int n0 = blockIdx.y * 64;
    int b  = blockIdx.z;

    const float* inb = in + (size_t)b * SEQ * CIN;
    int base = t0 * CIN;
    for (int i = tid; i < 128 * 32 + DIN; i += 256) {
        int gi = base + i;
        sIn[i] = (gi < SEQ * CIN) ? inb[gi] : 0.f;
    }
    __syncthreads();

    unsigned long long acc[8][2];
#pragma unroll
    for (int i = 0; i < 8; i++) { acc[i][0] = pk2(0.f, 0.f); acc[i][1] = pk2(0.f, 0.f); }

    for (int k0 = 0; k0 < DIN; k0 += 32) {
#pragma unroll
        for (int r = 0; r < 2; r++) {
            int j = tid * 8 + r * 4;
            int kk = j >> 6, nn = j & 63;
            *(float4*)&sB[kk][nn] =
                *(const float4*)&g_wc[(size_t)(k0 + kk) * G4 + n0 + nn];
        }
        __syncthreads();
#pragma unroll
        for (int k = 0; k < 32; k++) {
            ulonglong2 bb = *(const ulonglong2*)&sB[k][tx * 4];
#pragma unroll
            for (int i = 0; i < 8; i++) {
                float a = sIn[(ty * 8 + i) * CIN + k0 + k];
                unsigned long long aa = pk2(a, a);
                fma2(acc[i][0], aa, bb.x);
                fma2(acc[i][1], aa, bb.y);
            }
        }
        __syncthreads();
    }

    float4 bias = *(const float4*)&g_bias0[n0 + tx * 4];
    int tbase = t0 + ty * 8;
    if (tbase < XT) {
#pragma unroll
        for (int nn = 0; nn < 4; nn++) {
            float bv = (nn == 0) ? bias.x : (nn == 1) ? bias.y : (nn == 2) ? bias.z : bias.w;
            float v[8];
#pragma unroll
            for (int i = 0; i < 8; i++) {
                float2 p = unpk2(acc[i][nn >> 1]);
                v[i] = ((nn & 1) ? p.y : p.x) + bv;
            }
            float* dst = &g_xpre[((size_t)b * G4 + n0 + tx * 4 + nn) * XT + tbase];
            *(float4*)(dst)     = make_float4(v[0], v[1], v[2], v[3]);
            *(float4*)(dst + 4) = make_float4(v[4], v[5], v[6], v[7]);
        }
    }
}

// ---------------------------------------------------------------------------
// Kernel 3: input preactivations for layers 1..3 (transposed output).
// ---------------------------------------------------------------------------
__global__ void __launch_bounds__(256)
gemm_ih_kernel(const float* __restrict__ w_ih,
               const float* __restrict__ b_ih,
               const float* __restrict__ b_hh) {
    __shared__ __align__(16) float sA[64 * 64];
    __shared__ __align__(16) float sB[64 * 68];

    int tid = threadIdx.x;
    int tx = tid & 15, ty = tid >> 4;
    int t0 = blockIdx.x * 64;
    int n0 = blockIdx.y * 64;
    int b  = blockIdx.z;

    unsigned long long acc[4][2];
#pragma unroll
    for (int i = 0; i < 4; i++) { acc[i][0] = pk2(0.f, 0.f); acc[i][1] = pk2(0.f, 0.f); }

    for (int kt = 0; kt < 2; kt++) {
#pragma unroll
        for (int r = 0; r < 4; r++) {
            int j = tid * 16 + r * 4;
            int row = j >> 6, col = j & 63;
            int t = t0 + row;
            float4 v = make_float4(0.f, 0.f, 0.f, 0.f);
            if (t < L_OUT)
                v = *(const float4*)&g_hseq[((size_t)b * L_OUT + t) * HID + kt * 64 + col];
            *(float4*)&sA[row * 64 + col] = v;
        }
        for (int j = tid; j < 64 * 64; j += 256) {
            int n = j >> 6, kk = j & 63;
            sB[kk * 68 + n] = w_ih[(size_t)(n0 + n) * HID + kt * 64 + kk];
        }
        __syncthreads();
#pragma unroll
        for (int k = 0; k < 64; k++) {
            ulonglong2 bb = *(const ulonglong2*)&sB[k * 68 + tx * 4];
#pragma unroll
            for (int i = 0; i < 4; i++) {
                float a = sA[(ty * 4 + i) * 64 + k];
                unsigned long long aa = pk2(a, a);
                fma2(acc[i][0], aa, bb.x);
                fma2(acc[i][1], aa, bb.y);
            }
        }
        __syncthreads();
    }

    int n = n0 + tx * 4;
    float4 bias = make_float4(b_ih[n] + b_hh[n], b_ih[n + 1] + b_hh[n + 1],
                              b_ih[n + 2] + b_hh[n + 2], b_ih[n + 3] + b_hh[n + 3]);
    int tbase = t0 + ty * 4;
    if (tbase < XT) {
#pragma unroll
        for (int nn = 0; nn < 4; nn++) {
            float bv = (nn == 0) ? bias.x : (nn == 1) ? bias.y : (nn == 2) ? bias.z : bias.w;
            float v[4];
#pragma unroll
            for (int i = 0; i < 4; i++) {
                float2 p = unpk2(acc[i][nn >> 1]);
                v[i] = ((nn & 1) ? p.y : p.x) + bv;
            }
            float* dst = &g_xpre[((size_t)b * G4 + n + nn) * XT + tbase];
            *(float4*)(dst) = make_float4(v[0], v[1], v[2], v[3]);
        }
    }
}

// ---------------------------------------------------------------------------
// Kernel 4: recurrent scan — R1/R5 structure, but the 512 remote ops/step
// (256 st.shared::cluster + 256 remote mbarrier arrives) are replaced by ONE
// cp.async.bulk (1 KB, SMEM->peer DSMEM) signaling the peer's mbarrier via
// tx accounting, plus one local mbarrier.arrive.expect_tx per step.
//
// Per step per CTA:
//   all 256: compute gate act; STS to local staging stg[t&1][tid]
//   __syncthreads
//   tid0: expect_tx(1024) on LOCAL bar[t&1]; fence.proxy.async;
//         cp.async.bulk stg[t&1] -> peer gr[t&1], signaling PEER bar[t&1]
//   tid<128: wait bar[t&1] (parity (t>>1)&1) -> remote gates visible;
//            c,h from stg (own 2 gates) + gr (remote 2 gates); h_sh
//   __syncthreads
//
// Phase safety: a peer cannot run 2 phases ahead on one barrier (its t+2
// bulk needs its t+1 wait <- our t+1 bulk <- our t completion). tx-before-
// expect_tx within a phase is legal (signed tx count). Double-buffered
// stg/gr are protected by the same induction.
// ---------------------------------------------------------------------------
__global__ void __cluster_dims__(2, 1, 1) __launch_bounds__(256, 1)
scan_kernel(const float* __restrict__ w_hh) {
    __shared__ __align__(16) float h_sh[HID];
    __shared__ __align__(16) float stg[2][256];   // local gate staging (also local read buf)
    __shared__ __align__(16) float gr[2][256];    // remote gates landing
    __shared__ __align__(8) unsigned long long mbars[2];

    int tid  = threadIdx.x;
    int rank = blockIdx.x & 1;
    int b    = blockIdx.x >> 1;
    int g    = rank * 256 + tid;

    // recurrent weight row -> registers as f32x2 pairs
    unsigned long long w2[64];
    const ulonglong2* wr = (const ulonglong2*)(w_hh + (size_t)g * HID);
#pragma unroll
    for (int k = 0; k < 32; k++) {
        ulonglong2 u = wr[k];
        w2[2 * k]     = u.x;
        w2[2 * k + 1] = u.y;
    }

    if (tid < HID) h_sh[tid] = 0.f;
    unsigned bar0 = smem_u32(&mbars[0]);
    unsigned bar1 = smem_u32(&mbars[1]);
    if (tid == 0) { mbar_init(bar0, 1); mbar_init(bar1, 1); }
    __syncthreads();
    cluster_barrier();   // peer mbar init + h_sh visible cluster-wide

    unsigned peer = rank ^ 1;
    unsigned stg0 = smem_u32(&stg[0][0]);
    unsigned stg1 = smem_u32(&stg[1][0]);
    unsigned peer_gr0 = mapa_rank(smem_u32(&gr[0][0]), peer);
    unsigned peer_gr1 = mapa_rank(smem_u32(&gr[1][0]), peer);
    unsigned peer_b0  = mapa_rank(bar0, peer);
    unsigned peer_b1  = mapa_rank(bar1, peer);

    float c = 0.f;
    const size_t hrow = (size_t)b * L_OUT;
    const float* xrow_p = g_xpre + ((size_t)b * G4 + g) * XT;
    bool is_tanh_gate = (rank == 1) && (tid < HID);

    float4 xcur = *(const float4*)(xrow_p);
    float4 xnxt = *(const float4*)(xrow_p + 4);

    for (int t4 = 0; t4 < L_OUT; t4 += 4) {
        float4 xn2 = make_float4(0.f, 0.f, 0.f, 0.f);
        if (t4 + 8 < XT) xn2 = *(const float4*)(xrow_p + t4 + 8);

#pragma unroll
        for (int s = 0; s < 4; s++) {
            int t = t4 + s;
            float xp = (s == 0) ? xcur.x : (s == 1) ? xcur.y : (s == 2) ? xcur.z : xcur.w;

            // dot(w_row, h): 4 accumulators, packed f32x2
            unsigned long long a0 = pk2(0.f, 0.f), a1 = pk2(0.f, 0.f);
            unsigned long long a2 = pk2(0.f, 0.f), a3 = pk2(0.f, 0.f);
            const ulonglong2* h2 = (const ulonglong2*)h_sh;
#pragma unroll
            for (int k = 0; k < 16; k++) {
                ulonglong2 u = h2[2 * k];
                ulonglong2 v = h2[2 * k + 1];
                fma2(a0, w2[4 * k],     u.x);
                fma2(a1, w2[4 * k + 1], u.y);
                fma2(a2, w2[4 * k + 2], v.x);
                fma2(a3, w2[4 * k + 3], v.y);
            }
            float2 s0 = unpk2(a0), s1 = unpk2(a1), s2 = unpk2(a2), s3 = unpk2(a3);
            float pre = (((s0.x + s0.y) + (s1.x + s1.y)) +
                         ((s2.x + s2.y) + (s3.x + s3.y))) + xp;

            float act = is_tanh_gate ? fast_tanh(pre) : fast_sigmoid(pre);

            stg[t & 1][tid] = act;          // local staging (plain STS)
            __syncthreads();                // staging complete

            if (tid == 0) {
                unsigned lbar = (t & 1) ? bar1 : bar0;
                mbar_expect_tx(lbar, 1024); // arm local phase (count=1 arrive)
                fence_proxy_async_cta();    // order STS -> async-proxy read
                bulk_copy_to_peer((t & 1) ? peer_gr1 : peer_gr0,
                                  (t & 1) ? stg1 : stg0,
                                  1024,
                                  (t & 1) ? peer_b1 : peer_b0);
            }

            if (tid < HID) {
                mbar_wait_cluster((t & 1) ? bar1 : bar0, (unsigned)((t >> 1) & 1));
                const float* own = stg[t & 1];
                const float* rem = gr[t & 1];
                float iv, fv, gv, ov;
                if (rank == 0) { iv = own[tid]; fv = own[HID + tid];
                                 gv = rem[tid]; ov = rem[HID + tid]; }
                else           { gv = own[tid]; ov = own[HID + tid];
                                 iv = rem[tid]; fv = rem[HID + tid]; }
                c = fv * c + iv * gv;
                float h = ov * fast_tanh(c);
                h_sh[tid] = h;
                if (rank == 0)
                    g_hseq[(hrow + t) * HID + tid] = h;
            }
            __syncthreads();   // h_sh(t) ready for next dot
        }
        xcur = xnxt; xnxt = xn2;
    }
    cluster_barrier();
}

// ---------------------------------------------------------------------------
// Kernel 5: readout.
// ---------------------------------------------------------------------------
__global__ void out_kernel(const float* __restrict__ out_w,
                           const float* __restrict__ out_b,
                           float* __restrict__ out) {
    __shared__ float h[HID];
    int b = blockIdx.x;
    if (threadIdx.x < HID)
        h[threadIdx.x] = g_hseq[((size_t)b * L_OUT + (L_OUT - 1)) * HID + threadIdx.x];
    __syncthreads();
    if (threadIdx.x < LBL) {
        float acc = out_b[threadIdx.x];
        const float* wr = out_w + (size_t)threadIdx.x * HID;
#pragma unroll 8
        for (int k = 0; k < HID; k++) acc += wr[k] * h[k];
        out[(size_t)b * LBL + threadIdx.x] = acc;
    }
}

// ---------------------------------------------------------------------------
// Launch
// ---------------------------------------------------------------------------
extern "C" void kernel_launch(void* const* d_in, const int* in_sizes, int n_in,
                              void* d_out, int out_size) {
    const float* inputs    = (const float*)d_in[0];
    const float* proj_w    = (const float*)d_in[4];
    const float* proj_b    = (const float*)d_in[5];
    const float* w_ih0     = (const float*)d_in[6];
    const float* w_hh0     = (const float*)d_in[7];
    const float* b_ih0     = (const float*)d_in[8];
    const float* b_hh0     = (const float*)d_in[9];
    const float* w_ih_rest = (const float*)d_in[10];
    const float* w_hh_rest = (const float*)d_in[11];
    const float* b_ih_rest = (const float*)d_in[12];
    const float* b_hh_rest = (const float*)d_in[13];
    const float* out_w     = (const float*)d_in[14];
    const float* out_b     = (const float*)d_in[15];
    float* out = (float*)d_out;

    combine_kernel<<<dim3(DIN / 32, G4 / 32), dim3(32, 32)>>>(proj_w, w_ih0);
    bias0_kernel<<<1, G4>>>(proj_b, w_ih0, b_ih0, b_hh0);

    xpre0_kernel<<<dim3((L_OUT + 127) / 128, G4 / 64, BATCH), 256>>>(inputs);

    scan_kernel<<<BATCH * 2, 256>>>(w_hh0);

    for (int l = 0; l < 3; l++) {
        gemm_ih_kernel<<<dim3((L_OUT + 63) / 64, G4 / 64, BATCH), 256>>>(
            w_ih_rest + (size_t)l * G4 * HID,
            b_ih_rest + (size_t)l * G4,
            b_hh_rest + (size_t)l * G4);
        scan_kernel<<<BATCH * 2, 256>>>(w_hh_rest + (size_t)l * G4 * HID);
    }

    out_kernel<<<BATCH, 128>>>(out_w, out_b, out);
}